// round 16
// baseline (speedup 1.0000x reference)
#include <cuda_runtime.h>
#include <math.h>

// ---------------- problem constants ----------------
#define TLEN   2048
#define NSAMP  48            // B*C = 8*6
#define NCH    6
#define N1     80
#define NK     10
#define NCOEF  440
#define NT     256
#define SQ2H   0.70710678118654752f
#define TWO_PI 6.28318530717958648f
#define KB     4
#define NFULL2 80            // stage-2 pairs full-size (k = 1..4)
#define NWIN5  40            // k=5 windowed pairs (1024-pt)
#define NWIN   240           // k=6..9 windowed pairs (512-pt)
#define N1F    32            // j1 < 32: full-size stage 1
#define N1W    48            // j1 in [32,80): windowed stage 1
#define Y1     44            // stage-1 y-slots (32 full + 12 win)
#define Y2A    80            // stage-2 full y-slots
#define Y2B    20            // k=5 win y-slots
#define Y2C    60            // k=6..9 win y-slots

// ---------------- device scratch (static; no allocations) ----------------
__device__ __align__(16) float2 g_xh[NSAMP][TLEN];
__device__ __align__(16) float2 g_u1h[NSAMP][N1F][TLEN];
__device__ float g_uwr[NSAMP][N1W][512], g_uwi[NSAMP][N1W][512];
__device__ __align__(16) float g_psi1[N1F][TLEN];   // logical order
__device__ __align__(16) float g_psi2[NK][TLEN];    // logical order
__device__ int g_flag[NSAMP][N1];                   // producer-done flags

__device__ __forceinline__ int PF2(int e) { return e ^ ((e >> 3) & 14); }
__device__ __forceinline__ int SW5(int e) { return e ^ ((e >> 3) & 24); }
__device__ __forceinline__ int SW10(int e){ return e ^ ((e >> 3) & 56); }

// ---------------- full 8-point DFT (sgn=-1 fwd, +1 inv) ----------------
__device__ __forceinline__ void dft8(float xr[8], float xi[8], const float sgn) {
    float t0r = xr[0] + xr[4], t0i = xi[0] + xi[4];
    float t1r = xr[0] - xr[4], t1i = xi[0] - xi[4];
    float t2r = xr[2] + xr[6], t2i = xi[2] + xi[6];
    float t3r = xr[2] - xr[6], t3i = xi[2] - xi[6];
    float it3r = -sgn * t3i, it3i = sgn * t3r;
    float E0r = t0r + t2r, E0i = t0i + t2i;
    float E2r = t0r - t2r, E2i = t0i - t2i;
    float E1r = t1r + it3r, E1i = t1i + it3i;
    float E3r = t1r - it3r, E3i = t1i - it3i;
    float u0r = xr[1] + xr[5], u0i = xi[1] + xi[5];
    float u1r = xr[1] - xr[5], u1i = xi[1] - xi[5];
    float u2r = xr[3] + xr[7], u2i = xi[3] + xi[7];
    float u3r = xr[3] - xr[7], u3i = xi[3] - xi[7];
    float iu3r = -sgn * u3i, iu3i = sgn * u3r;
    float O0r = u0r + u2r, O0i = u0i + u2i;
    float O2r = u0r - u2r, O2i = u0i - u2i;
    float O1r = u1r + iu3r, O1i = u1i + iu3i;
    float O3r = u1r - iu3r, O3i = u1i - iu3i;
    float w1i = sgn * SQ2H;
    float a1r = O1r * SQ2H - O1i * w1i, a1i = O1r * w1i + O1i * SQ2H;
    float a2r = -sgn * O2i,             a2i = sgn * O2r;
    float a3r = -O3r * SQ2H - O3i * w1i, a3i = O3r * w1i - O3i * SQ2H;
    xr[0] = E0r + O0r; xi[0] = E0i + O0i;
    xr[4] = E0r - O0r; xi[4] = E0i - O0i;
    xr[1] = E1r + a1r; xi[1] = E1i + a1i;
    xr[5] = E1r - a1r; xi[5] = E1i - a1i;
    xr[2] = E2r + a2r; xi[2] = E2i + a2i;
    xr[6] = E2r - a2r; xi[6] = E2i - a2i;
    xr[3] = E3r + a3r; xi[3] = E3i + a3i;
    xr[7] = E3r - a3r; xi[7] = E3i - a3i;
}

__device__ __forceinline__ void twiddle8(float xr[8], float xi[8],
                                         const float c, const float s) {
    float cr = c, ci = s;
#pragma unroll
    for (int t = 1; t < 8; t++) {
        float r = xr[t] * cr - xi[t] * ci;
        xi[t] = xr[t] * ci + xi[t] * cr; xr[t] = r;
        float nr = cr * c - ci * s; ci = cr * s + ci * c; cr = nr;
    }
}

// Mid radix-8 pass over float2 smem (L = 256 or 32). DIF fwd / DIT inv.
__device__ __forceinline__ void pass8_f2(float2* sm, const int L,
                                         const float sgn, const bool dit) {
    const int S = L >> 3;
    const int t = threadIdx.x;
    const int j = t & (S - 1);
    const int base = ((t & ~(S - 1)) << 3) + j;
    float xr[8], xi[8];
#pragma unroll
    for (int m = 0; m < 8; m++) {
        float2 v = sm[PF2(base + m * S)];
        xr[m] = v.x; xi[m] = v.y;
    }
    float ws, wc;
    __sincosf((float)j * (sgn * TWO_PI / (float)L), &ws, &wc);
    if (dit) { twiddle8(xr, xi, wc, ws); dft8(xr, xi, sgn); }
    else     { dft8(xr, xi, sgn); twiddle8(xr, xi, wc, ws); }
#pragma unroll
    for (int m = 0; m < 8; m++)
        sm[PF2(base + m * S)] = make_float2(xr[m], xi[m]);
}

__device__ __forceinline__ void b4c(float2 v[4], const float sgn) {
    float t0r = v[0].x + v[2].x, t0i = v[0].y + v[2].y;
    float t1r = v[0].x - v[2].x, t1i = v[0].y - v[2].y;
    float t2r = v[1].x + v[3].x, t2i = v[1].y + v[3].y;
    float t3r = v[1].x - v[3].x, t3i = v[1].y - v[3].y;
    float it3r = -sgn * t3i, it3i = sgn * t3r;
    v[0] = make_float2(t0r + t2r, t0i + t2i);
    v[2] = make_float2(t0r - t2r, t0i - t2i);
    v[1] = make_float2(t1r + it3r, t1i + it3i);
    v[3] = make_float2(t1r - it3r, t1i - it3i);
}

__device__ __forceinline__ void prologue_f2(float2* sm, const float2* spec,
                                            const float* psi) {
    const int t = threadIdx.x;
#pragma unroll
    for (int h = 0; h < 2; h++) {
        int c = t + h * NT;
        float4 f0 = ((const float4*)spec)[2 * c];
        float4 f1 = ((const float4*)spec)[2 * c + 1];
        float4 pq = ((const float4*)psi)[c];
        float2 v[4];
        v[0] = make_float2(f0.x * pq.x, f0.y * pq.x);
        v[1] = make_float2(f0.z * pq.y, f0.w * pq.y);
        v[2] = make_float2(f1.x * pq.z, f1.y * pq.z);
        v[3] = make_float2(f1.z * pq.w, f1.w * pq.w);
        b4c(v, 1.0f);
        int p = PF2(4 * c);
        sm[p]       = v[0];
        sm[p + 1]   = v[1];
        sm[p ^ 2]       = v[2];
        sm[(p ^ 2) + 1] = v[3];
    }
}

__device__ __forceinline__ void real_dft4(const float U[8],
                                          const float wc, const float ws,
                                          float pr[KB], float pi[KB]) {
    float a0 = U[0] + U[4], a1 = U[1] + U[5], a2 = U[2] + U[6], a3 = U[3] + U[7];
    float d0 = U[0] - U[4], d1 = U[1] - U[5], d2 = U[2] - U[6], d3 = U[3] - U[7];
    float s13 = SQ2H * (d1 + d3), m13 = SQ2H * (d1 - d3);
    float y0r = (a0 + a2) + (a1 + a3);
    float y1r = d0 + m13,  y1i = -d2 - s13;
    float y2r = a0 - a2,   y2i = a3 - a1;
    float y3r = d0 - m13,  y3i = d2 - s13;
    float w2r = wc * wc - ws * ws, w2i = -2.0f * wc * ws;
    float w3r = w2r * wc + w2i * ws, w3i = -w2r * ws + w2i * wc;
    pr[0] = y0r;                          pi[0] = 0.0f;
    pr[1] = y1r * wc + y1i * ws;          pi[1] = -y1r * ws + y1i * wc;
    pr[2] = y2r * w2r - y2i * w2i;        pi[2] = y2r * w2i + y2i * w2r;
    pr[3] = y3r * w3r - y3i * w3i;        pi[3] = y3r * w3i + y3i * w3r;
}

__device__ __forceinline__ void tail_lite_f2(const float2* sm, const float scale,
                                             float pr[KB], float pi[KB],
                                             float& owc, float& ows) {
    const int t = threadIdx.x;
    float xr[8], xi[8];
#pragma unroll
    for (int m = 0; m < 8; m++) {
        float2 v = sm[PF2(t + 256 * m)];
        xr[m] = v.x; xi[m] = v.y;
    }
    float ws, wc;
    __sincosf((float)t * (TWO_PI / 2048.0f), &ws, &wc);
    owc = wc; ows = ws;
    twiddle8(xr, xi, wc, ws);
    dft8(xr, xi, 1.0f);
    float U[8];
#pragma unroll
    for (int s = 0; s < 8; s++)
        U[s] = sqrtf(xr[s] * xr[s] + xi[s] * xi[s]) * scale;
    real_dft4(U, wc, ws, pr, pi);
}

__device__ __forceinline__ void tail_full_f2(float2* sm, const float scale,
                                             float pr[KB], float pi[KB],
                                             float& owc, float& ows) {
    const int t = threadIdx.x;
    float xr[8], xi[8];
#pragma unroll
    for (int m = 0; m < 8; m++) {
        float2 v = sm[PF2(t + 256 * m)];
        xr[m] = v.x; xi[m] = v.y;
    }
    float ws, wc;
    __sincosf((float)t * (TWO_PI / 2048.0f), &ws, &wc);
    owc = wc; ows = ws;
    twiddle8(xr, xi, wc, ws);
    dft8(xr, xi, 1.0f);
#pragma unroll
    for (int s = 0; s < 8; s++) {
        xr[s] = sqrtf(xr[s] * xr[s] + xi[s] * xi[s]) * scale;
        xi[s] = 0.0f;
    }
    dft8(xr, xi, -1.0f);
    twiddle8(xr, xi, wc, -ws);
#pragma unroll
    for (int k = 0; k < KB; k++) { pr[k] = xr[k]; pi[k] = xi[k]; }
#pragma unroll
    for (int m = 0; m < 8; m++)
        sm[PF2(t + 256 * m)] = make_float2(xr[m], xi[m]);
}

__device__ __forceinline__ void bins_store(const float pr[KB], const float pi[KB],
                                           float* scratch) {
    const int t = threadIdx.x;
    scratch[t]          = pr[0];
    scratch[NT + t]     = pr[1];
    scratch[2 * NT + t] = pr[2];
    scratch[3 * NT + t] = pr[3];
    scratch[4 * NT + t] = pi[1];
    scratch[5 * NT + t] = pi[2];
    scratch[6 * NT + t] = pi[3];
}
__device__ __forceinline__ void bins_sum(const float* scratch, float* cb) {
    const int w = threadIdx.x >> 5, l = threadIdx.x & 31;
    if (w < 7) {
        float s = 0.0f;
#pragma unroll
        for (int m = 0; m < 8; m++) s += scratch[w * NT + l + 32 * m];
#pragma unroll
        for (int o = 16; o; o >>= 1) s += __shfl_xor_sync(0xFFFFFFFFu, s, o);
        if (l == 0) cb[w] = s;
    }
}

#define PH1 0.29502258f
#define PH2 0.0075757135f
#define PH3 1.6931630e-5f
__device__ __constant__ float C8c[8] = {1.f, SQ2H, 0.f, -SQ2H, -1.f, -SQ2H, 0.f, SQ2H};
__device__ __constant__ float S8c[8] = {0.f, SQ2H, 1.f, SQ2H, 0.f, -SQ2H, -1.f, -SQ2H};
#define CP8 0.92387953251f
#define SP8 0.38268343236f
__device__ __constant__ float C16t[16] = { 1.f,  CP8,  SQ2H,  SP8, 0.f, -SP8, -SQ2H, -CP8,
                                          -1.f, -CP8, -SQ2H, -SP8, 0.f,  SP8,  SQ2H,  CP8};
__device__ __constant__ float S16t[16] = { 0.f,  SP8,  SQ2H,  CP8, 1.f,  CP8,  SQ2H,  SP8,
                                           0.f, -SP8, -SQ2H, -CP8, -1.f, -CP8, -SQ2H, -SP8};

__device__ __forceinline__ void bins_finish(const float* cb, const float wc,
                                            const float ws, float* redm,
                                            float* out_elem) {
    const int t = threadIdx.x;
    const float invT = 1.0f / (float)TLEN;
    float d0 = cb[0];
    float c1r = cb[1], c2r = cb[2], c3r = cb[3];
    float c1i = cb[4], c2i = cb[5], c3i = cb[6];
    float e2r = wc * wc - ws * ws, e2i = 2.0f * wc * ws;
    float e3r = e2r * wc - e2i * ws, e3i = e2r * ws + e2i * wc;
    float d1r = (c1r * wc - c1i * ws) * PH1, d1i = (c1r * ws + c1i * wc) * PH1;
    float d2r = (c2r * e2r - c2i * e2i) * PH2, d2i = (c2r * e2i + c2i * e2r) * PH2;
    float d3r = (c3r * e3r - c3i * e3i) * PH3, d3i = (c3r * e3i + c3i * e3r) * PH3;
    float s = 0.0f;
#pragma unroll
    for (int m = 0; m < 8; m++) {
        float acc = d1r * C8c[m] - d1i * S8c[m]
                  + d2r * C8c[(2 * m) & 7] - d2i * S8c[(2 * m) & 7]
                  + d3r * C8c[(3 * m) & 7] - d3i * S8c[(3 * m) & 7];
        s += __logf((d0 + 2.0f * acc) * invT + 1e-6f);
    }
#pragma unroll
    for (int o = 16; o; o >>= 1) s += __shfl_xor_sync(0xFFFFFFFFu, s, o);
    if ((t & 31) == 0) redm[t >> 5] = s;
    __syncthreads();
    if (t == 0) {
        float tot = 0.0f;
#pragma unroll
        for (int w = 0; w < 8; w++) tot += redm[w];
        *out_elem = tot * invT;
    }
}

__device__ __forceinline__ int UW_SLOT(int b) {
    return (b & 7) + 64 * ((b >> 3) & 7) + 8 * ((b >> 6) & 7);
}
__device__ __forceinline__ int LOG_IDX(int kb) {
    int a = kb & 7, b = (kb >> 3) & 7, c = (kb >> 6) & 7, d = (kb >> 9) & 3;
    return (a << 8) | (b << 5) | (c << 2) | d;
}
__device__ __forceinline__ void spin_flag(const int n, const int j1) {
    volatile int* f = &g_flag[n][j1];
    while (*f == 0) __nanosleep(64);
}

// =================== kernel A: filter init + flag zero + forward FFT of x ===================
__global__ void __launch_bounds__(NT) prep_kernel(const float* __restrict__ x) {
    __shared__ __align__(16) float pool[2 * TLEN];
    if (blockIdx.x >= NSAMP) {
        int L = (blockIdx.x - NSAMP) * NT + threadIdx.x;   // 0..2047
        // zero producer flags (3840 ints)
        for (int q = L; q < NSAMP * N1; q += TLEN) ((int*)g_flag)[q] = 0;
        int a = L >> 8, b = (L >> 5) & 7, c = (L >> 2) & 7, d = L & 3;
        int k = a + 8 * b + 64 * c + 512 * d;
        float f = (float)(k < 1024 ? k : k - 2048) / 2048.0f;
        for (int j = 0; j < N1F; j++) {
            float xi  = 0.4f * exp2f(-(float)j / 8.0f);
            float sig = 0.8f * xi / 8.0f;
            float dd  = f - xi;
            g_psi1[j][L] = expf(-dd * dd / (2.0f * sig * sig));
        }
        for (int kk = 0; kk < NK; kk++) {
            float xi  = 0.4f * exp2f(-(float)kk);
            float sig = 0.8f * xi;
            float dd  = f - xi;
            g_psi2[kk][L] = expf(-dd * dd / (2.0f * sig * sig));
        }
        return;
    }
    float2* sm = (float2*)pool;
    const int n = blockIdx.x, b = n / NCH, ch = n % NCH;
    const int t = threadIdx.x;
    {
        float xr[8], xi[8];
#pragma unroll
        for (int s = 0; s < 8; s++) {
            xr[s] = x[(b * TLEN + t + 256 * s) * NCH + ch];
            xi[s] = 0.0f;
        }
        float ws, wc;
        __sincosf((float)t * (-TWO_PI / 2048.0f), &ws, &wc);
        dft8(xr, xi, -1.0f);
        twiddle8(xr, xi, wc, ws);
#pragma unroll
        for (int s = 0; s < 8; s++)
            sm[PF2(t + 256 * s)] = make_float2(xr[s], xi[s]);
    }
    __syncthreads();
    pass8_f2(sm, 256, -1.0f, false); __syncthreads();
    pass8_f2(sm, 32,  -1.0f, false); __syncthreads();
#pragma unroll
    for (int h = 0; h < 2; h++) {
        int c = t + h * NT;
        int p = PF2(4 * c);
        float2 v[4];
        v[0] = sm[p];
        v[1] = sm[p + 1];
        v[2] = sm[p ^ 2];
        v[3] = sm[(p ^ 2) + 1];
        b4c(v, -1.0f);
        ((float4*)g_xh[n])[2 * c]     = make_float4(v[0].x, v[0].y, v[1].x, v[1].y);
        ((float4*)g_xh[n])[2 * c + 1] = make_float4(v[2].x, v[2].y, v[3].x, v[3].y);
    }
}

// =================== mega kernel: stage 1 producers + stage 2 consumers ===================
__global__ void __launch_bounds__(NT, 6) mega_kernel(float* __restrict__ out) {
    __shared__ __align__(16) float pool[2 * TLEN];
    __shared__ float cb[8];
    __shared__ float redm[8];
    __shared__ float scw[8][7];
    const int n = blockIdx.x;
    const int tid = threadIdx.x;
    const float invT = 1.0f / 2048.0f;
    if (blockIdx.y < N1F) {
        // ------- stage 1 full-size (producer) -------
        float2* sm = (float2*)pool;
        const int j = blockIdx.y;
        float pr[KB], pi[KB], wc, ws;
        prologue_f2(sm, g_xh[n], g_psi1[j]);  __syncthreads();
        pass8_f2(sm, 32,  1.0f, true);        __syncthreads();
        pass8_f2(sm, 256, 1.0f, true);        __syncthreads();
        tail_full_f2(sm, invT, pr, pi, wc, ws); __syncthreads();
        pass8_f2(sm, 256, -1.0f, false);      __syncthreads();
        pass8_f2(sm, 32,  -1.0f, false);      __syncthreads();
#pragma unroll
        for (int h = 0; h < 2; h++) {
            int c = tid + h * NT;
            int p = PF2(4 * c);
            float2 v[4];
            v[0] = sm[p];
            v[1] = sm[p + 1];
            v[2] = sm[p ^ 2];
            v[3] = sm[(p ^ 2) + 1];
            b4c(v, -1.0f);
            ((float4*)g_u1h[n][j])[2 * c]     = make_float4(v[0].x, v[0].y, v[1].x, v[1].y);
            ((float4*)g_u1h[n][j])[2 * c + 1] = make_float4(v[2].x, v[2].y, v[3].x, v[3].y);
        }
        __threadfence();
        __syncthreads();
        if (tid == 0) atomicExch(&g_flag[n][j], 1);   // publish U1h
        bins_store(pr, pi, pool);        __syncthreads();
        bins_sum(pool, cb);              __syncthreads();
        bins_finish(cb, wc, ws, redm,
                    &out[((n / NCH) * NCOEF + j) * NCH + (n % NCH)]);
        return;
    }
    if (blockIdx.y < Y1) {
        // ------- stage 1 windowed (producer), 4 groups of 64 threads -------
        const int g = tid >> 6, u = tid & 63;
        const int warp = tid >> 5, lane = tid & 31;
        const int j1 = N1F + (blockIdx.y - N1F) * 4 + g;   // 32..79
        float* RE = pool + g * 512;
        float* IM = pool + TLEN + g * 512;
        float* redw = redm;
        float xr[8], xi[8];
        const float cj  = 819.2f * exp2f(-(float)j1 * 0.125f);
        const float sgm = 0.1f * cj;
        const int b_lo  = (int)floorf(cj - 6.0f * sgm);
        {
            const int base = (u >> 3) + ((u & 7) << 3);
            const float i2s = 1.0f / (2.0f * sgm * sgm);
            float v0r, v0i, v1r, v1i;
#pragma unroll
            for (int h = 0; h < 2; h++) {
                int bin = b_lo + base + 64 * h;
                float dd = (float)bin - cj;
                float ps = expf(-dd * dd * i2s);
                float2 v = g_xh[n][LOG_IDX(bin & 2047)];
                float vr = v.x * ps, vi = v.y * ps;
                if (h == 0) { v0r = vr; v0i = vi; } else { v1r = vr; v1i = vi; }
            }
#pragma unroll
            for (int s = 0; s < 8; s++) {
                xr[s] = v0r + C8c[s] * v1r - S8c[s] * v1i;
                xi[s] = v0i + C8c[s] * v1i + S8c[s] * v1r;
            }
            int p0 = SW5(8 * u);
            ((float4*)(RE + p0))[0] = make_float4(xr[0], xr[1], xr[2], xr[3]);
            ((float4*)(RE + p0))[1] = make_float4(xr[4], xr[5], xr[6], xr[7]);
            ((float4*)(IM + p0))[0] = make_float4(xi[0], xi[1], xi[2], xi[3]);
            ((float4*)(IM + p0))[1] = make_float4(xi[4], xi[5], xi[6], xi[7]);
        }
        __syncthreads();
        {
            int j = u & 7;
            int base = ((u >> 3) << 6) + j;
#pragma unroll
            for (int m = 0; m < 8; m++) { int p = SW5(base + 8 * m); xr[m] = RE[p]; xi[m] = IM[p]; }
            float ws2, wc2;
            __sincosf((float)j * (TWO_PI / 64.0f), &ws2, &wc2);
            twiddle8(xr, xi, wc2, ws2);
            dft8(xr, xi, 1.0f);
#pragma unroll
            for (int m = 0; m < 8; m++) { int p = SW5(base + 8 * m); RE[p] = xr[m]; IM[p] = xi[m]; }
        }
        __syncthreads();
        float pr[KB], pi[KB], wc, ws;
        {
#pragma unroll
            for (int m = 0; m < 8; m++) { int p = SW5(u + 64 * m); xr[m] = RE[p]; xi[m] = IM[p]; }
            __sincosf((float)u * (TWO_PI / 512.0f), &ws, &wc);
            twiddle8(xr, xi, wc, ws);
            dft8(xr, xi, 1.0f);
#pragma unroll
            for (int m = 0; m < 8; m++) {
                xr[m] = sqrtf(xr[m] * xr[m] + xi[m] * xi[m]) * invT;
                xi[m] = 0.0f;
            }
            dft8(xr, xi, -1.0f);
            twiddle8(xr, xi, wc, -ws);
#pragma unroll
            for (int k = 0; k < KB; k++) { pr[k] = xr[k]; pi[k] = xi[k]; }
        }
        __syncthreads();
        {
            int p0 = SW5(8 * u);
            ((float4*)(RE + p0))[0] = make_float4(xr[0], xr[1], xr[2], xr[3]);
            ((float4*)(RE + p0))[1] = make_float4(xr[4], xr[5], xr[6], xr[7]);
            ((float4*)(IM + p0))[0] = make_float4(xi[0], xi[1], xi[2], xi[3]);
            ((float4*)(IM + p0))[1] = make_float4(xi[4], xi[5], xi[6], xi[7]);
        }
        __syncthreads();
        {
            int j = u >> 3;
#pragma unroll
            for (int d = 0; d < 8; d++) { int p = SW5(u + 64 * d); xr[d] = RE[p]; xi[d] = IM[p]; }
            float ws2, wc2;
            __sincosf((float)j * (TWO_PI / 64.0f), &ws2, &wc2);
            dft8(xr, xi, -1.0f);
            twiddle8(xr, xi, wc2, -ws2);
#pragma unroll
            for (int b1 = 0; b1 < 8; b1++) { int p = SW5(u + 64 * b1); RE[p] = xr[b1]; IM[p] = xi[b1]; }
        }
        __syncthreads();
        {
            int base = (u & 7) + 64 * (u >> 3);
#pragma unroll
            for (int j = 0; j < 8; j++) { int p = SW5(base + 8 * j); xr[j] = RE[p]; xi[j] = IM[p]; }
            dft8(xr, xi, -1.0f);
#pragma unroll
            for (int b2 = 0; b2 < 8; b2++) { int p = SW5(base + 8 * b2); RE[p] = xr[b2]; IM[p] = xi[b2]; }
        }
        __syncthreads();
        if (j1 < 72) {
#pragma unroll
            for (int t2 = 0; t2 < 8; t2++) {
                int i = u + 64 * t2;
                g_uwr[n][j1 - N1F][i] = RE[SW5(i)];
                g_uwi[n][j1 - N1F][i] = IM[SW5(i)];
            }
            __threadfence();
        }
        {
            float rows[7] = {pr[0], pr[1], pr[2], pr[3], pi[1], pi[2], pi[3]};
#pragma unroll
            for (int r = 0; r < 7; r++) {
                float v = rows[r];
#pragma unroll
                for (int o = 16; o; o >>= 1) v += __shfl_xor_sync(0xFFFFFFFFu, v, o);
                if (lane == 0) scw[warp][r] = v;
            }
        }
        __syncthreads();
        if (u == 0 && j1 < 72) atomicExch(&g_flag[n][j1], 1);   // publish subsampled U1h
        {
            float cbv[7];
#pragma unroll
            for (int r = 0; r < 7; r++)
                cbv[r] = 4.0f * (scw[2 * g][r] + scw[2 * g + 1][r]);
            float d0 = cbv[0];
            float c1r = cbv[1], c2r = cbv[2], c3r = cbv[3];
            float c1i = cbv[4], c2i = cbv[5], c3i = cbv[6];
            float e2r = wc * wc - ws * ws, e2i = 2.0f * wc * ws;
            float e3r = e2r * wc - e2i * ws, e3i = e2r * ws + e2i * wc;
            float d1r = (c1r * wc - c1i * ws) * PH1, d1i = (c1r * ws + c1i * wc) * PH1;
            float d2r = (c2r * e2r - c2i * e2i) * PH2, d2i = (c2r * e2i + c2i * e2r) * PH2;
            float d3r = (c3r * e3r - c3i * e3i) * PH3, d3i = (c3r * e3i + c3i * e3r) * PH3;
            float s = 0.0f;
#pragma unroll
            for (int m = 0; m < 8; m++) {
                float acc = d1r * C8c[m] - d1i * S8c[m]
                          + d2r * C8c[(2 * m) & 7] - d2i * S8c[(2 * m) & 7]
                          + d3r * C8c[(3 * m) & 7] - d3i * S8c[(3 * m) & 7];
                s += __logf((d0 + 2.0f * acc) * invT + 1e-6f);
            }
#pragma unroll
            for (int o = 16; o; o >>= 1) s += __shfl_xor_sync(0xFFFFFFFFu, s, o);
            if (lane == 0) redw[warp] = s;
        }
        __syncthreads();
        if (u == 0) {
            float tot = (redw[2 * g] + redw[2 * g + 1]) * (1.0f / 512.0f);
            out[((n / NCH) * NCOEF + j1) * NCH + (n % NCH)] = tot;
        }
        return;
    }
    const int y2 = blockIdx.y - Y1;
    float* redw = redm;
    if (y2 < Y2A) {
        // ------- stage 2 full-size (consumer): pairs with k = 1..4 -------
        float2* sm = (float2*)pool;
        const int pid = y2;
        int k = 1, pp = pid;
        while (pp >= 8 * k) { pp -= 8 * k; k++; }
        const int j1 = pp;
        if (tid == 0) spin_flag(n, j1);
        __syncthreads();
        float pr[KB], pi[KB], wc, ws;
        prologue_f2(sm, g_u1h[n][j1], g_psi2[k]); __syncthreads();
        pass8_f2(sm, 32,  1.0f, true);  __syncthreads();
        pass8_f2(sm, 256, 1.0f, true);  __syncthreads();
        tail_lite_f2(sm, invT, pr, pi, wc, ws);
        __syncthreads();
        bins_store(pr, pi, pool);        __syncthreads();
        bins_sum(pool, cb);              __syncthreads();
        bins_finish(cb, wc, ws, redm,
                    &out[((n / NCH) * NCOEF + N1 + pid) * NCH + (n % NCH)]);
        return;
    }
    if (y2 < Y2A + Y2B) {
        // ------- k=5 windowed (consumer): 1024-pt, 2 groups x 128 thr -------
        const int g = tid >> 7, u = tid & 127;
        const int warp = tid >> 5, lane = tid & 31;
        const int j1 = (y2 - Y2A) * 2 + g;
        if (tid < 2) spin_flag(n, (y2 - Y2A) * 2 + tid);
        __syncthreads();
        float* RE = pool + g * 1024;
        float* IM = pool + TLEN + g * 1024;
        {
            const int beta = (u >> 3) + ((u & 7) << 4);
            const float xic = 0.0125f;
            const float i2s = 5000.0f;
            float v0r, v0i, v1r, v1i;
#pragma unroll
            for (int h2 = 0; h2 < 2; h2++) {
                int bin = -98 + beta + 128 * h2;
                float f = (float)bin / 2048.0f;
                float dd = f - xic;
                float ps = expf(-dd * dd * i2s);
                float vr, vi;
                if (j1 < N1F) {
                    float2 v = g_u1h[n][j1][LOG_IDX(bin & 2047)];
                    vr = v.x * ps; vi = v.y * ps;
                } else {
                    int s5 = UW_SLOT(bin & 511);
                    vr = 4.0f * g_uwr[n][j1 - N1F][s5] * ps;
                    vi = 4.0f * g_uwi[n][j1 - N1F][s5] * ps;
                }
                if (h2 == 0) { v0r = vr; v0i = vi; } else { v1r = vr; v1i = vi; }
            }
            float xr[8], xi[8];
#pragma unroll
            for (int s = 0; s < 8; s++) {
                xr[s] = v0r + C8c[s] * v1r - S8c[s] * v1i;
                xi[s] = v0i + C8c[s] * v1i + S8c[s] * v1r;
            }
            int base = SW10(8 * u);
            ((float4*)(RE + base))[0] = make_float4(xr[0], xr[1], xr[2], xr[3]);
            ((float4*)(RE + base))[1] = make_float4(xr[4], xr[5], xr[6], xr[7]);
            ((float4*)(IM + base))[0] = make_float4(xi[0], xi[1], xi[2], xi[3]);
            ((float4*)(IM + base))[1] = make_float4(xi[4], xi[5], xi[6], xi[7]);
        }
        __syncthreads();
        {
            int gam = u >> 3, j = u & 7;
            int base = 64 * gam + j;
            float xr[8], xi[8];
#pragma unroll
            for (int d = 0; d < 8; d++) { int p = SW10(base + 8 * d); xr[d] = RE[p]; xi[d] = IM[p]; }
            float ws2, wc2;
            __sincosf((float)j * (TWO_PI / 64.0f), &ws2, &wc2);
            twiddle8(xr, xi, wc2, ws2);
            dft8(xr, xi, 1.0f);
#pragma unroll
            for (int d = 0; d < 8; d++) { int p = SW10(base + 8 * d); RE[p] = xr[d]; IM[p] = xi[d]; }
        }
        __syncthreads();
        float pr[KB], pi[KB], wrc, wrs;
        {
            const int r = u & 63, h = u >> 6;
            const int j = r & 7, m = r >> 3;
            float sn, cs;
            __sincosf((float)r * (TWO_PI / 1024.0f), &sn, &cs);
            wrc = cs; wrs = sn;
            float er[8], ei[8], qr[8], qi[8];
            float cr = 1.0f, ci = 0.0f;
#pragma unroll
            for (int gm = 0; gm < 16; gm++) {
                int p = SW10(64 * gm + 8 * m + j);
                float br = RE[p], bi = IM[p];
                float tr = br * cr - bi * ci;
                float ti = br * ci + bi * cr;
                if ((gm & 1) == 0) { er[gm >> 1] = tr; ei[gm >> 1] = ti; }
                else               { qr[gm >> 1] = tr; qi[gm >> 1] = ti; }
                float nc = cr * wrc - ci * wrs; ci = cr * wrs + ci * wrc; cr = nc;
            }
            dft8(er, ei, 1.0f);
            dft8(qr, qi, 1.0f);
            float sg = h ? -1.0f : 1.0f;
            float U[8];
#pragma unroll
            for (int s = 0; s < 8; s++) {
                float wr = sg * C16t[s], wi = sg * S16t[s];
                float zr = er[s] + wr * qr[s] - wi * qi[s];
                float zi = ei[s] + wr * qi[s] + wi * qr[s];
                U[s] = sqrtf(zr * zr + zi * zi) * invT;
            }
            float I0 = 0.f, I1r = 0.f, I1i = 0.f, I2r = 0.f, I2i = 0.f, I3r = 0.f, I3i = 0.f;
#pragma unroll
            for (int s = 0; s < 8; s++) {
                I0  += U[s];
                I1r += U[s] * C16t[s];            I1i -= U[s] * S16t[s];
                I2r += U[s] * C16t[(2 * s) & 15]; I2i -= U[s] * S16t[(2 * s) & 15];
                I3r += U[s] * C16t[(3 * s) & 15]; I3i -= U[s] * S16t[(3 * s) & 15];
            }
            float w1r = wrc, w1i = -wrs;
            float w2r = w1r * w1r - w1i * w1i, w2i = 2.0f * w1r * w1i;
            float w3r = w2r * w1r - w2i * w1i, w3i = w2r * w1i + w2i * w1r;
            float sg2 = h ? -1.0f : 1.0f;
            pr[0] = I0;                                   pi[0] = 0.0f;
            pr[1] = sg2 * (I1r * w1r - I1i * w1i);        pi[1] = sg2 * (I1r * w1i + I1i * w1r);
            pr[2] = (I2r * w2r - I2i * w2i);              pi[2] = (I2r * w2i + I2i * w2r);
            pr[3] = sg2 * (I3r * w3r - I3i * w3i);        pi[3] = sg2 * (I3r * w3i + I3i * w3r);
        }
        {
            float rows[7] = {pr[0], pr[1], pr[2], pr[3], pi[1], pi[2], pi[3]};
#pragma unroll
            for (int rr = 0; rr < 7; rr++) {
                float v = rows[rr];
#pragma unroll
                for (int o = 16; o; o >>= 1) v += __shfl_xor_sync(0xFFFFFFFFu, v, o);
                if (lane == 0) scw[warp][rr] = v;
            }
        }
        __syncthreads();
        {
            const int h = u >> 6;
            float cbv[7];
#pragma unroll
            for (int rr = 0; rr < 7; rr++)
                cbv[rr] = 2.0f * (scw[4 * g][rr] + scw[4 * g + 1][rr]
                                + scw[4 * g + 2][rr] + scw[4 * g + 3][rr]);
            float sg = h ? -1.0f : 1.0f;
            float e1r = wrc, e1i = wrs;
            float e2r = e1r * e1r - e1i * e1i, e2i = 2.0f * e1r * e1i;
            float e3r = e2r * e1r - e2i * e1i, e3i = e2r * e1i + e2i * e1r;
            float d0 = cbv[0];
            float d1r = sg * PH1 * (cbv[1] * e1r - cbv[4] * e1i);
            float d1i = sg * PH1 * (cbv[1] * e1i + cbv[4] * e1r);
            float d2r = PH2 * (cbv[2] * e2r - cbv[5] * e2i);
            float d2i = PH2 * (cbv[2] * e2i + cbv[5] * e2r);
            float d3r = sg * PH3 * (cbv[3] * e3r - cbv[6] * e3i);
            float d3i = sg * PH3 * (cbv[3] * e3i + cbv[6] * e3r);
            float s = 0.0f;
#pragma unroll
            for (int sI = 0; sI < 8; sI++) {
                float acc = d1r * C16t[sI] - d1i * S16t[sI]
                          + d2r * C16t[(2 * sI) & 15] - d2i * S16t[(2 * sI) & 15]
                          + d3r * C16t[(3 * sI) & 15] - d3i * S16t[(3 * sI) & 15];
                s += __logf((d0 + 2.0f * acc) * invT + 1e-6f);
            }
#pragma unroll
            for (int o = 16; o; o >>= 1) s += __shfl_xor_sync(0xFFFFFFFFu, s, o);
            if (lane == 0) redw[warp] = s;
        }
        __syncthreads();
        if (u == 0) {
            float tot = (redw[4 * g] + redw[4 * g + 1] + redw[4 * g + 2] + redw[4 * g + 3])
                        * (1.0f / 1024.0f);
            out[((n / NCH) * NCOEF + N1 + NFULL2 + j1) * NCH + (n % NCH)] = tot;
        }
        return;
    }
    // ------- k=6..9 windowed (consumer): 512-pt path, 4 groups x 64 thr -------
    {
        const int g = tid >> 6, u = tid & 63;
        const int warp = tid >> 5, lane = tid & 31;
        const int wp = (y2 - Y2A - Y2B) * 4 + g;            // 0..239
        int k, j1;
        if (wp < 48)       { k = 6; j1 = wp; }
        else if (wp < 104) { k = 7; j1 = wp - 48; }
        else if (wp < 168) { k = 8; j1 = wp - 104; }
        else               { k = 9; j1 = wp - 168; }
        if (tid < 4) {
            int wpq = (y2 - Y2A - Y2B) * 4 + tid;
            int jq = (wpq < 48) ? wpq : (wpq < 104) ? wpq - 48
                   : (wpq < 168) ? wpq - 104 : wpq - 168;
            spin_flag(n, jq);
        }
        __syncthreads();
        const int b_lo = (k == 6) ? -49 : (k == 7) ? -26 : (k == 8) ? -13 : -7;
        float* RE = pool + g * 512;
        float* IM = pool + TLEN + g * 512;
        float xr[8], xi[8];
        {
            const int base = (u >> 3) + ((u & 7) << 3);
            const float xic = 0.4f * exp2f(-(float)k);
            const float sg = 0.8f * xic;
            const float i2s = 1.0f / (2.0f * sg * sg);
            float v0r, v0i, v1r, v1i;
#pragma unroll
            for (int h = 0; h < 2; h++) {
                int bin = b_lo + base + 64 * h;
                float f = (float)bin / 2048.0f;
                float dd = f - xic;
                float ps = expf(-dd * dd * i2s);
                float vr, vi;
                if (j1 < N1F) {
                    float2 v = g_u1h[n][j1][LOG_IDX(bin & 2047)];
                    vr = v.x * ps; vi = v.y * ps;
                } else {
                    int s5 = UW_SLOT(bin & 511);
                    vr = 4.0f * g_uwr[n][j1 - N1F][s5] * ps;
                    vi = 4.0f * g_uwi[n][j1 - N1F][s5] * ps;
                }
                if (h == 0) { v0r = vr; v0i = vi; } else { v1r = vr; v1i = vi; }
            }
#pragma unroll
            for (int s = 0; s < 8; s++) {
                xr[s] = v0r + C8c[s] * v1r - S8c[s] * v1i;
                xi[s] = v0i + C8c[s] * v1i + S8c[s] * v1r;
            }
        }
        {
            int p0 = SW5(8 * u);
            ((float4*)(RE + p0))[0] = make_float4(xr[0], xr[1], xr[2], xr[3]);
            ((float4*)(RE + p0))[1] = make_float4(xr[4], xr[5], xr[6], xr[7]);
            ((float4*)(IM + p0))[0] = make_float4(xi[0], xi[1], xi[2], xi[3]);
            ((float4*)(IM + p0))[1] = make_float4(xi[4], xi[5], xi[6], xi[7]);
        }
        __syncthreads();
        {
            int j = u & 7;
            int base = ((u >> 3) << 6) + j;
#pragma unroll
            for (int m = 0; m < 8; m++) { int p = SW5(base + 8 * m); xr[m] = RE[p]; xi[m] = IM[p]; }
            float ws2, wc2;
            __sincosf((float)j * (TWO_PI / 64.0f), &ws2, &wc2);
            twiddle8(xr, xi, wc2, ws2);
            dft8(xr, xi, 1.0f);
#pragma unroll
            for (int m = 0; m < 8; m++) { int p = SW5(base + 8 * m); RE[p] = xr[m]; IM[p] = xi[m]; }
        }
        __syncthreads();
        float pr[KB], pi[KB], wc, ws;
        {
#pragma unroll
            for (int m = 0; m < 8; m++) { int p = SW5(u + 64 * m); xr[m] = RE[p]; xi[m] = IM[p]; }
            __sincosf((float)u * (TWO_PI / 512.0f), &ws, &wc);
            twiddle8(xr, xi, wc, ws);
            dft8(xr, xi, 1.0f);
            float U[8];
#pragma unroll
            for (int s = 0; s < 8; s++)
                U[s] = sqrtf(xr[s] * xr[s] + xi[s] * xi[s]) * invT;
            real_dft4(U, wc, ws, pr, pi);
        }
        {
            float rows[7] = {pr[0], pr[1], pr[2], pr[3], pi[1], pi[2], pi[3]};
#pragma unroll
            for (int r = 0; r < 7; r++) {
                float v = rows[r];
#pragma unroll
                for (int o = 16; o; o >>= 1) v += __shfl_xor_sync(0xFFFFFFFFu, v, o);
                if (lane == 0) scw[warp][r] = v;
            }
        }
        __syncthreads();
        {
            float cbv[7];
#pragma unroll
            for (int r = 0; r < 7; r++)
                cbv[r] = 4.0f * (scw[2 * g][r] + scw[2 * g + 1][r]);
            float d0 = cbv[0];
            float c1r = cbv[1], c2r = cbv[2], c3r = cbv[3];
            float c1i = cbv[4], c2i = cbv[5], c3i = cbv[6];
            float e2r = wc * wc - ws * ws, e2i = 2.0f * wc * ws;
            float e3r = e2r * wc - e2i * ws, e3i = e2r * ws + e2i * wc;
            float d1r = (c1r * wc - c1i * ws) * PH1, d1i = (c1r * ws + c1i * wc) * PH1;
            float d2r = (c2r * e2r - c2i * e2i) * PH2, d2i = (c2r * e2i + c2i * e2r) * PH2;
            float d3r = (c3r * e3r - c3i * e3i) * PH3, d3i = (c3r * e3i + c3i * e3r) * PH3;
            float s = 0.0f;
#pragma unroll
            for (int m = 0; m < 8; m++) {
                float acc = d1r * C8c[m] - d1i * S8c[m]
                          + d2r * C8c[(2 * m) & 7] - d2i * S8c[(2 * m) & 7]
                          + d3r * C8c[(3 * m) & 7] - d3i * S8c[(3 * m) & 7];
                s += __logf((d0 + 2.0f * acc) * invT + 1e-6f);
            }
#pragma unroll
            for (int o = 16; o; o >>= 1) s += __shfl_xor_sync(0xFFFFFFFFu, s, o);
            if (lane == 0) redw[warp] = s;
        }
        __syncthreads();
        if (u == 0) {
            float tot = (redw[2 * g] + redw[2 * g + 1]) * (1.0f / 512.0f);
            out[((n / NCH) * NCOEF + N1 + NFULL2 + NWIN5 + wp) * NCH + (n % NCH)] = tot;
        }
    }
}

// ---------------- launcher ----------------
extern "C" void kernel_launch(void* const* d_in, const int* in_sizes, int n_in,
                              void* d_out, int out_size) {
    const float* x = (const float*)d_in[0];   // [8, 2048, 6] f32
    float* out = (float*)d_out;               // [8, 440, 6] f32
    prep_kernel<<<NSAMP + TLEN / NT, NT>>>(x);
    mega_kernel<<<dim3(NSAMP, Y1 + Y2A + Y2B + Y2C), NT>>>(out);
}

// round 17
// speedup vs baseline: 1.0311x; 1.0311x over previous
#include <cuda_runtime.h>
#include <math.h>

// ---------------- problem constants ----------------
#define TLEN   2048
#define NSAMP  48            // B*C = 8*6
#define NCH    6
#define N1     80
#define NK     10
#define NCOEF  440
#define NT     256
#define SQ2H   0.70710678118654752f
#define TWO_PI 6.28318530717958648f
#define KB     4
#define NFULL2 80            // stage-2 pairs full-size (k = 1..4)
#define NWIN5  40            // k=5 windowed pairs (1024-pt)
#define NWIN   240           // k=6..9 windowed pairs (512-pt)
#define N1F    32            // j1 < 32: full-size stage 1
#define N1W    48            // j1 in [32,80): windowed stage 1
#define NFILT  42            // filter-init CTA rows (32 psi1 + 10 psi2)

// ---------------- device scratch (static; no allocations) ----------------
// Frequency-domain arrays stored in SWIZZLED-DIGIT-REVERSED physical order.
__device__ float g_xh_re[NSAMP][TLEN], g_xh_im[NSAMP][TLEN];
__device__ float g_u1h_re[NSAMP][N1F][TLEN], g_u1h_im[NSAMP][N1F][TLEN];
__device__ float g_uwr[NSAMP][N1W][512], g_uwi[NSAMP][N1W][512];
__device__ float g_psi1[N1F][TLEN];
__device__ float g_psi2[NK][TLEN];

__device__ __forceinline__ int SW(int i)  { return i ^ ((i >> 3) & 28); }
__device__ __forceinline__ int SW5(int e) { return e ^ ((e >> 3) & 24); }
__device__ __forceinline__ int SW10(int e){ return e ^ ((e >> 3) & 56); }

// ---------------- full 8-point DFT (sgn=-1 fwd, +1 inv) ----------------
__device__ __forceinline__ void dft8(float xr[8], float xi[8], const float sgn) {
    float t0r = xr[0] + xr[4], t0i = xi[0] + xi[4];
    float t1r = xr[0] - xr[4], t1i = xi[0] - xi[4];
    float t2r = xr[2] + xr[6], t2i = xi[2] + xi[6];
    float t3r = xr[2] - xr[6], t3i = xi[2] - xi[6];
    float it3r = -sgn * t3i, it3i = sgn * t3r;
    float E0r = t0r + t2r, E0i = t0i + t2i;
    float E2r = t0r - t2r, E2i = t0i - t2i;
    float E1r = t1r + it3r, E1i = t1i + it3i;
    float E3r = t1r - it3r, E3i = t1i - it3i;
    float u0r = xr[1] + xr[5], u0i = xi[1] + xi[5];
    float u1r = xr[1] - xr[5], u1i = xi[1] - xi[5];
    float u2r = xr[3] + xr[7], u2i = xi[3] + xi[7];
    float u3r = xr[3] - xr[7], u3i = xi[3] - xi[7];
    float iu3r = -sgn * u3i, iu3i = sgn * u3r;
    float O0r = u0r + u2r, O0i = u0i + u2i;
    float O2r = u0r - u2r, O2i = u0i - u2i;
    float O1r = u1r + iu3r, O1i = u1i + iu3i;
    float O3r = u1r - iu3r, O3i = u1i - iu3i;
    float w1i = sgn * SQ2H;
    float a1r = O1r * SQ2H - O1i * w1i, a1i = O1r * w1i + O1i * SQ2H;
    float a2r = -sgn * O2i,             a2i = sgn * O2r;
    float a3r = -O3r * SQ2H - O3i * w1i, a3i = O3r * w1i - O3i * SQ2H;
    xr[0] = E0r + O0r; xi[0] = E0i + O0i;
    xr[4] = E0r - O0r; xi[4] = E0i - O0i;
    xr[1] = E1r + a1r; xi[1] = E1i + a1i;
    xr[5] = E1r - a1r; xi[5] = E1i - a1i;
    xr[2] = E2r + a2r; xi[2] = E2i + a2i;
    xr[6] = E2r - a2r; xi[6] = E2i - a2i;
    xr[3] = E3r + a3r; xi[3] = E3i + a3i;
    xr[7] = E3r - a3r; xi[7] = E3i - a3i;
}

__device__ __forceinline__ void twiddle8(float xr[8], float xi[8],
                                         const float c, const float s) {
    float cr = c, ci = s;
#pragma unroll
    for (int t = 1; t < 8; t++) {
        float r = xr[t] * cr - xi[t] * ci;
        xi[t] = xr[t] * ci + xi[t] * cr; xr[t] = r;
        float nr = cr * c - ci * s; ci = cr * s + ci * c; cr = nr;
    }
}

__device__ __forceinline__ void load8(const float* a, int base, int S, float v[8]) {
#pragma unroll
    for (int t = 0; t < 8; t++) v[t] = a[SW(base + t * S)];
}
__device__ __forceinline__ void store8(float* a, int base, int S, const float v[8]) {
#pragma unroll
    for (int t = 0; t < 8; t++) a[SW(base + t * S)] = v[t];
}

__device__ __forceinline__ void pass8_mid(float* re, float* im, const int L,
                                          const float sgn, const bool dit) {
    const int S = L >> 3;
    const int tid = threadIdx.x;
    const int j = tid & (S - 1);
    const int base = ((tid & ~(S - 1)) << 3) + j;
    float xr[8], xi[8];
    load8(re, base, S, xr); load8(im, base, S, xi);
    float ws, wc;
    __sincosf((float)j * (sgn * TWO_PI / (float)L), &ws, &wc);
    if (dit) { twiddle8(xr, xi, wc, ws); dft8(xr, xi, sgn); }
    else     { dft8(xr, xi, sgn); twiddle8(xr, xi, wc, ws); }
    store8(re, base, S, xr); store8(im, base, S, xi);
}

__device__ __forceinline__ void b4(float4& r, float4& q, const float sgn) {
    float t0r = r.x + r.z, t0i = q.x + q.z;
    float t1r = r.x - r.z, t1i = q.x - q.z;
    float t2r = r.y + r.w, t2i = q.y + q.w;
    float t3r = r.y - r.w, t3i = q.y - q.w;
    float it3r = -sgn * t3i, it3i = sgn * t3r;
    r.x = t0r + t2r;  q.x = t0i + t2i;
    r.z = t0r - t2r;  q.z = t0i - t2i;
    r.y = t1r + it3r; q.y = t1i + it3i;
    r.w = t1r - it3r; q.w = t1i - it3i;
}

__device__ __forceinline__ void prologue(float* re, float* im,
                                         const float* sr, const float* si,
                                         const float* psi) {
    const int tid = threadIdx.x;
#pragma unroll
    for (int h = 0; h < 2; h++) {
        int c = tid + h * NT;
        int p = SW(c << 2);
        int g = p >> 2;
        float4 ar = ((const float4*)sr)[g];
        float4 ai = ((const float4*)si)[g];
        float4 ps = ((const float4*)psi)[g];
        float4 r, q;
        r.x = ar.x * ps.x; r.y = ar.y * ps.y; r.z = ar.z * ps.z; r.w = ar.w * ps.w;
        q.x = ai.x * ps.x; q.y = ai.y * ps.y; q.z = ai.z * ps.z; q.w = ai.w * ps.w;
        b4(r, q, 1.0f);
        *(float4*)(re + p) = r;
        *(float4*)(im + p) = q;
    }
}

__device__ __forceinline__ void real_dft4(const float U[8],
                                          const float wc, const float ws,
                                          float pr[KB], float pi[KB]) {
    float a0 = U[0] + U[4], a1 = U[1] + U[5], a2 = U[2] + U[6], a3 = U[3] + U[7];
    float d0 = U[0] - U[4], d1 = U[1] - U[5], d2 = U[2] - U[6], d3 = U[3] - U[7];
    float s13 = SQ2H * (d1 + d3), m13 = SQ2H * (d1 - d3);
    float y0r = (a0 + a2) + (a1 + a3);
    float y1r = d0 + m13,  y1i = -d2 - s13;
    float y2r = a0 - a2,   y2i = a3 - a1;
    float y3r = d0 - m13,  y3i = d2 - s13;
    float w2r = wc * wc - ws * ws, w2i = -2.0f * wc * ws;
    float w3r = w2r * wc + w2i * ws, w3i = -w2r * ws + w2i * wc;
    pr[0] = y0r;                          pi[0] = 0.0f;
    pr[1] = y1r * wc + y1i * ws;          pi[1] = -y1r * ws + y1i * wc;
    pr[2] = y2r * w2r - y2i * w2i;        pi[2] = y2r * w2i + y2i * w2r;
    pr[3] = y3r * w3r - y3i * w3i;        pi[3] = y3r * w3i + y3i * w3r;
}

__device__ __forceinline__ void tail_lite(const float* re, const float* im,
                                          const float scale,
                                          float pr[KB], float pi[KB],
                                          float& owc, float& ows) {
    const int t = threadIdx.x;
    float xr[8], xi[8];
    load8(re, t, 256, xr); load8(im, t, 256, xi);
    float ws, wc;
    __sincosf((float)t * (TWO_PI / 2048.0f), &ws, &wc);
    owc = wc; ows = ws;
    twiddle8(xr, xi, wc, ws);
    dft8(xr, xi, 1.0f);
    float U[8];
#pragma unroll
    for (int s = 0; s < 8; s++)
        U[s] = sqrtf(xr[s] * xr[s] + xi[s] * xi[s]) * scale;
    real_dft4(U, wc, ws, pr, pi);
}

__device__ __forceinline__ void tail_full(float* re, float* im, const float scale,
                                          float pr[KB], float pi[KB],
                                          float& owc, float& ows) {
    const int t = threadIdx.x;
    float xr[8], xi[8];
    load8(re, t, 256, xr); load8(im, t, 256, xi);
    float ws, wc;
    __sincosf((float)t * (TWO_PI / 2048.0f), &ws, &wc);
    owc = wc; ows = ws;
    twiddle8(xr, xi, wc, ws);
    dft8(xr, xi, 1.0f);
#pragma unroll
    for (int s = 0; s < 8; s++) {
        xr[s] = sqrtf(xr[s] * xr[s] + xi[s] * xi[s]) * scale;
        xi[s] = 0.0f;
    }
    dft8(xr, xi, -1.0f);
    twiddle8(xr, xi, wc, -ws);
#pragma unroll
    for (int k = 0; k < KB; k++) { pr[k] = xr[k]; pi[k] = xi[k]; }
    store8(re, t, 256, xr); store8(im, t, 256, xi);
}

__device__ __forceinline__ void bins_store(const float pr[KB], const float pi[KB],
                                           float* scratch) {
    const int t = threadIdx.x;
    scratch[t]          = pr[0];
    scratch[NT + t]     = pr[1];
    scratch[2 * NT + t] = pr[2];
    scratch[3 * NT + t] = pr[3];
    scratch[4 * NT + t] = pi[1];
    scratch[5 * NT + t] = pi[2];
    scratch[6 * NT + t] = pi[3];
}
__device__ __forceinline__ void bins_sum(const float* scratch, float* cb) {
    const int w = threadIdx.x >> 5, l = threadIdx.x & 31;
    if (w < 7) {
        float s = 0.0f;
#pragma unroll
        for (int m = 0; m < 8; m++) s += scratch[w * NT + l + 32 * m];
#pragma unroll
        for (int o = 16; o; o >>= 1) s += __shfl_xor_sync(0xFFFFFFFFu, s, o);
        if (l == 0) cb[w] = s;
    }
}

#define PH1 0.29502258f
#define PH2 0.0075757135f
#define PH3 1.6931630e-5f
__device__ __constant__ float C8c[8] = {1.f, SQ2H, 0.f, -SQ2H, -1.f, -SQ2H, 0.f, SQ2H};
__device__ __constant__ float S8c[8] = {0.f, SQ2H, 1.f, SQ2H, 0.f, -SQ2H, -1.f, -SQ2H};
#define CP8 0.92387953251f
#define SP8 0.38268343236f
__device__ __constant__ float C16t[16] = { 1.f,  CP8,  SQ2H,  SP8, 0.f, -SP8, -SQ2H, -CP8,
                                          -1.f, -CP8, -SQ2H, -SP8, 0.f,  SP8,  SQ2H,  CP8};
__device__ __constant__ float S16t[16] = { 0.f,  SP8,  SQ2H,  CP8, 1.f,  CP8,  SQ2H,  SP8,
                                           0.f, -SP8, -SQ2H, -CP8, -1.f, -CP8, -SQ2H, -SP8};

__device__ __forceinline__ void bins_finish(const float* cb, const float wc,
                                            const float ws, float* redm,
                                            float* out_elem) {
    const int t = threadIdx.x;
    const float invT = 1.0f / (float)TLEN;
    float d0 = cb[0];
    float c1r = cb[1], c2r = cb[2], c3r = cb[3];
    float c1i = cb[4], c2i = cb[5], c3i = cb[6];
    float e2r = wc * wc - ws * ws, e2i = 2.0f * wc * ws;
    float e3r = e2r * wc - e2i * ws, e3i = e2r * ws + e2i * wc;
    float d1r = (c1r * wc - c1i * ws) * PH1, d1i = (c1r * ws + c1i * wc) * PH1;
    float d2r = (c2r * e2r - c2i * e2i) * PH2, d2i = (c2r * e2i + c2i * e2r) * PH2;
    float d3r = (c3r * e3r - c3i * e3i) * PH3, d3i = (c3r * e3i + c3i * e3r) * PH3;
    float s = 0.0f;
#pragma unroll
    for (int m = 0; m < 8; m++) {
        float acc = d1r * C8c[m] - d1i * S8c[m]
                  + d2r * C8c[(2 * m) & 7] - d2i * S8c[(2 * m) & 7]
                  + d3r * C8c[(3 * m) & 7] - d3i * S8c[(3 * m) & 7];
        s += __logf((d0 + 2.0f * acc) * invT + 1e-6f);
    }
#pragma unroll
    for (int o = 16; o; o >>= 1) s += __shfl_xor_sync(0xFFFFFFFFu, s, o);
    if ((t & 31) == 0) redm[t >> 5] = s;
    __syncthreads();
    if (t == 0) {
        float tot = 0.0f;
#pragma unroll
        for (int w = 0; w < 8; w++) tot += redm[w];
        *out_elem = tot * invT;
    }
}

__device__ __forceinline__ int UW_SLOT(int b) {
    return (b & 7) + 64 * ((b >> 3) & 7) + 8 * ((b >> 6) & 7);
}

// =================== kernel A: filter init (per-row CTAs) + FFT of x ===================
__global__ void __launch_bounds__(NT) prep_kernel(const float* __restrict__ x) {
    __shared__ __align__(16) float pool[2 * TLEN];
    if (blockIdx.x >= NSAMP) {
        // one CTA per filter row; each thread does 8 positions
        const int r = blockIdx.x - NSAMP;      // 0..41
        float xi, sig;
        if (r < N1F) { xi = 0.4f * exp2f(-(float)r / 8.0f); sig = 0.8f * xi / 8.0f; }
        else         { xi = 0.4f * exp2f(-(float)(r - N1F)); sig = 0.8f * xi; }
        const float i2s = 1.0f / (2.0f * sig * sig);
#pragma unroll
        for (int s = 0; s < 8; s++) {
            int p = threadIdx.x + NT * s;      // physical slot
            int i = SW(p);                     // logical DIF index
            int a = i >> 8, b = (i >> 5) & 7, c = (i >> 2) & 7, d = i & 3;
            int k = a + 8 * b + 64 * c + 512 * d;
            float f = (float)(k < 1024 ? k : k - 2048) / 2048.0f;
            float dd = f - xi;
            float v = __expf(-dd * dd * i2s);
            if (r < N1F) g_psi1[r][p] = v;
            else         g_psi2[r - N1F][p] = v;
        }
        return;
    }
    float* sre = pool;
    float* sim = pool + TLEN;
    const int n = blockIdx.x, b = n / NCH, ch = n % NCH;
    const int t = threadIdx.x;
    {
        float xr[8], xi[8];
#pragma unroll
        for (int s = 0; s < 8; s++) {
            xr[s] = x[(b * TLEN + t + 256 * s) * NCH + ch];
            xi[s] = 0.0f;
        }
        float ws, wc;
        __sincosf((float)t * (-TWO_PI / 2048.0f), &ws, &wc);
        dft8(xr, xi, -1.0f);
        twiddle8(xr, xi, wc, ws);
        store8(sre, t, 256, xr); store8(sim, t, 256, xi);
    }
    __syncthreads();
    pass8_mid(sre, sim, 256, -1.0f, false); __syncthreads();
    pass8_mid(sre, sim, 32,  -1.0f, false); __syncthreads();
#pragma unroll
    for (int h = 0; h < 2; h++) {
        int c = t + h * NT;
        int p = SW(c << 2);
        int g = p >> 2;
        float4 r = *(float4*)(sre + p);
        float4 q = *(float4*)(sim + p);
        b4(r, q, -1.0f);
        ((float4*)g_xh_re[n])[g] = r;
        ((float4*)g_xh_im[n])[g] = q;
    }
}

// =================== kernel B: stage 1 (full j<32 | windowed j in [32,80)) ===================
__global__ void __launch_bounds__(NT, 6) stage1m_kernel(float* __restrict__ out) {
    __shared__ __align__(16) float pool[2 * TLEN];
    __shared__ float cb[8];
    __shared__ float redm[8];
    __shared__ float scw[8][7];
    const int n = blockIdx.x;
    const int t = threadIdx.x;
    const float invT = 1.0f / (float)TLEN;
    if (blockIdx.y < N1F) {
        // ------- full-size stage 1 -------
        float* sre = pool;
        float* sim = pool + TLEN;
        const int j = blockIdx.y;
        float pr[KB], pi[KB], wc, ws;
        prologue(sre, sim, g_xh_re[n], g_xh_im[n], g_psi1[j]);  __syncthreads();
        pass8_mid(sre, sim, 32,  1.0f, true);   __syncthreads();
        pass8_mid(sre, sim, 256, 1.0f, true);   __syncthreads();
        tail_full(sre, sim, invT, pr, pi, wc, ws); __syncthreads();
        pass8_mid(sre, sim, 256, -1.0f, false);  __syncthreads();
        pass8_mid(sre, sim, 32,  -1.0f, false);  __syncthreads();
#pragma unroll
        for (int h = 0; h < 2; h++) {
            int c = t + h * NT;
            int p = SW(c << 2);
            int g = p >> 2;
            float4 r = *(float4*)(sre + p);
            float4 q = *(float4*)(sim + p);
            b4(r, q, -1.0f);
            ((float4*)g_u1h_re[n][j])[g] = r;
            ((float4*)g_u1h_im[n][j])[g] = q;
        }
        __syncthreads();
        bins_store(pr, pi, sre);         __syncthreads();
        bins_sum(sre, cb);               __syncthreads();
        bins_finish(cb, wc, ws, redm,
                    &out[((n / NCH) * NCOEF + j) * NCH + (n % NCH)]);
        return;
    }
    // ------- windowed stage 1 (512-pt), 4 groups of 64 threads -------
    const int g = t >> 6, u = t & 63;
    const int warp = t >> 5, lane = t & 31;
    const int j1 = N1F + (blockIdx.y - N1F) * 4 + g;   // 32..79
    const float invT5 = 1.0f / 2048.0f;
    float* RE = pool + g * 512;
    float* IM = pool + TLEN + g * 512;
    float* redw = redm;
    float xr[8], xi[8];
    const float cj  = 819.2f * exp2f(-(float)j1 * 0.125f);
    const float sgm = 0.1f * cj;
    const int b_lo  = (int)floorf(cj - 6.0f * sgm);
    {
        const int base = (u >> 3) + ((u & 7) << 3);
        const float i2s = 1.0f / (2.0f * sgm * sgm);
        float v0r, v0i, v1r, v1i;
#pragma unroll
        for (int h = 0; h < 2; h++) {
            int bin = b_lo + base + 64 * h;
            float dd = (float)bin - cj;
            float ps = __expf(-dd * dd * i2s);
            int kb = bin & 2047;
            int a = kb & 7, b = (kb >> 3) & 7, c = (kb >> 6) & 7, d = (kb >> 9) & 3;
            int p = SW((a << 8) | (b << 5) | (c << 2) | d);
            float vr = g_xh_re[n][p] * ps;
            float vi = g_xh_im[n][p] * ps;
            if (h == 0) { v0r = vr; v0i = vi; } else { v1r = vr; v1i = vi; }
        }
#pragma unroll
        for (int s = 0; s < 8; s++) {
            xr[s] = v0r + C8c[s] * v1r - S8c[s] * v1i;
            xi[s] = v0i + C8c[s] * v1i + S8c[s] * v1r;
        }
        int p0 = SW5(8 * u);
        ((float4*)(RE + p0))[0] = make_float4(xr[0], xr[1], xr[2], xr[3]);
        ((float4*)(RE + p0))[1] = make_float4(xr[4], xr[5], xr[6], xr[7]);
        ((float4*)(IM + p0))[0] = make_float4(xi[0], xi[1], xi[2], xi[3]);
        ((float4*)(IM + p0))[1] = make_float4(xi[4], xi[5], xi[6], xi[7]);
    }
    __syncthreads();
    {
        int j = u & 7;
        int base = ((u >> 3) << 6) + j;
#pragma unroll
        for (int m = 0; m < 8; m++) { int p = SW5(base + 8 * m); xr[m] = RE[p]; xi[m] = IM[p]; }
        float ws2, wc2;
        __sincosf((float)j * (TWO_PI / 64.0f), &ws2, &wc2);
        twiddle8(xr, xi, wc2, ws2);
        dft8(xr, xi, 1.0f);
#pragma unroll
        for (int m = 0; m < 8; m++) { int p = SW5(base + 8 * m); RE[p] = xr[m]; IM[p] = xi[m]; }
    }
    __syncthreads();
    float pr[KB], pi[KB], wc, ws;
    {
#pragma unroll
        for (int m = 0; m < 8; m++) { int p = SW5(u + 64 * m); xr[m] = RE[p]; xi[m] = IM[p]; }
        __sincosf((float)u * (TWO_PI / 512.0f), &ws, &wc);
        twiddle8(xr, xi, wc, ws);
        dft8(xr, xi, 1.0f);
#pragma unroll
        for (int m = 0; m < 8; m++) {
            xr[m] = sqrtf(xr[m] * xr[m] + xi[m] * xi[m]) * invT5;
            xi[m] = 0.0f;
        }
        dft8(xr, xi, -1.0f);
        twiddle8(xr, xi, wc, -ws);
#pragma unroll
        for (int k = 0; k < KB; k++) { pr[k] = xr[k]; pi[k] = xi[k]; }
    }
    __syncthreads();
    {
        int p0 = SW5(8 * u);
        ((float4*)(RE + p0))[0] = make_float4(xr[0], xr[1], xr[2], xr[3]);
        ((float4*)(RE + p0))[1] = make_float4(xr[4], xr[5], xr[6], xr[7]);
        ((float4*)(IM + p0))[0] = make_float4(xi[0], xi[1], xi[2], xi[3]);
        ((float4*)(IM + p0))[1] = make_float4(xi[4], xi[5], xi[6], xi[7]);
    }
    __syncthreads();
    {
        int j = u >> 3;
#pragma unroll
        for (int d = 0; d < 8; d++) { int p = SW5(u + 64 * d); xr[d] = RE[p]; xi[d] = IM[p]; }
        float ws2, wc2;
        __sincosf((float)j * (TWO_PI / 64.0f), &ws2, &wc2);
        dft8(xr, xi, -1.0f);
        twiddle8(xr, xi, wc2, -ws2);
#pragma unroll
        for (int b1 = 0; b1 < 8; b1++) { int p = SW5(u + 64 * b1); RE[p] = xr[b1]; IM[p] = xi[b1]; }
    }
    __syncthreads();
    {
        int base = (u & 7) + 64 * (u >> 3);
#pragma unroll
        for (int j = 0; j < 8; j++) { int p = SW5(base + 8 * j); xr[j] = RE[p]; xi[j] = IM[p]; }
        dft8(xr, xi, -1.0f);
#pragma unroll
        for (int b2 = 0; b2 < 8; b2++) { int p = SW5(base + 8 * b2); RE[p] = xr[b2]; IM[p] = xi[b2]; }
    }
    __syncthreads();
    if (j1 < 72) {
#pragma unroll
        for (int t2 = 0; t2 < 8; t2++) {
            int i = u + 64 * t2;
            g_uwr[n][j1 - N1F][i] = RE[SW5(i)];
            g_uwi[n][j1 - N1F][i] = IM[SW5(i)];
        }
    }
    {
        float rows[7] = {pr[0], pr[1], pr[2], pr[3], pi[1], pi[2], pi[3]};
#pragma unroll
        for (int r = 0; r < 7; r++) {
            float v = rows[r];
#pragma unroll
            for (int o = 16; o; o >>= 1) v += __shfl_xor_sync(0xFFFFFFFFu, v, o);
            if (lane == 0) scw[warp][r] = v;
        }
    }
    __syncthreads();
    {
        float cbv[7];
#pragma unroll
        for (int r = 0; r < 7; r++)
            cbv[r] = 4.0f * (scw[2 * g][r] + scw[2 * g + 1][r]);
        float d0 = cbv[0];
        float c1r = cbv[1], c2r = cbv[2], c3r = cbv[3];
        float c1i = cbv[4], c2i = cbv[5], c3i = cbv[6];
        float e2r = wc * wc - ws * ws, e2i = 2.0f * wc * ws;
        float e3r = e2r * wc - e2i * ws, e3i = e2r * ws + e2i * wc;
        float d1r = (c1r * wc - c1i * ws) * PH1, d1i = (c1r * ws + c1i * wc) * PH1;
        float d2r = (c2r * e2r - c2i * e2i) * PH2, d2i = (c2r * e2i + c2i * e2r) * PH2;
        float d3r = (c3r * e3r - c3i * e3i) * PH3, d3i = (c3r * e3i + c3i * e3r) * PH3;
        float s = 0.0f;
#pragma unroll
        for (int m = 0; m < 8; m++) {
            float acc = d1r * C8c[m] - d1i * S8c[m]
                      + d2r * C8c[(2 * m) & 7] - d2i * S8c[(2 * m) & 7]
                      + d3r * C8c[(3 * m) & 7] - d3i * S8c[(3 * m) & 7];
            s += __logf((d0 + 2.0f * acc) * invT5 + 1e-6f);
        }
#pragma unroll
        for (int o = 16; o; o >>= 1) s += __shfl_xor_sync(0xFFFFFFFFu, s, o);
        if (lane == 0) redw[warp] = s;
    }
    __syncthreads();
    if (u == 0) {
        float tot = (redw[2 * g] + redw[2 * g + 1]) * (1.0f / 512.0f);
        out[((n / NCH) * NCOEF + j1) * NCH + (n % NCH)] = tot;
    }
}

// =================== kernel C: stage 2 (full | k=5 win | k=6..9 win) ===================
__global__ void __launch_bounds__(NT, 6) stage2m_kernel(float* __restrict__ out) {
    __shared__ __align__(16) float pool[2 * TLEN];
    __shared__ float cb[8];
    __shared__ float redm[8];
    __shared__ float scw[8][7];
    const int n = blockIdx.x;
    const int tid = threadIdx.x;
    const float invT = 1.0f / 2048.0f;
    if (blockIdx.y < NFULL2) {
        // ------- full-size: pairs with k = 1..4 (j1 < 32) -------
        float* sre = pool;
        float* sim = pool + TLEN;
        const int pid = blockIdx.y;
        int k = 1, pp = pid;
        while (pp >= 8 * k) { pp -= 8 * k; k++; }
        const int j1 = pp;
        float pr[KB], pi[KB], wc, ws;
        prologue(sre, sim, g_u1h_re[n][j1], g_u1h_im[n][j1], g_psi2[k]); __syncthreads();
        pass8_mid(sre, sim, 32,  1.0f, true);  __syncthreads();
        pass8_mid(sre, sim, 256, 1.0f, true);  __syncthreads();
        tail_lite(sre, sim, invT, pr, pi, wc, ws);
        __syncthreads();
        bins_store(pr, pi, sre);         __syncthreads();
        bins_sum(sre, cb);               __syncthreads();
        bins_finish(cb, wc, ws, redm,
                    &out[((n / NCH) * NCOEF + N1 + pid) * NCH + (n % NCH)]);
        return;
    }
    float* redw = redm;
    if (blockIdx.y < NFULL2 + NWIN5 / 2) {
        // ------- k=5 windowed: 256-bin window, 1024-pt, 2 groups x 128 thr -------
        const int g = tid >> 7, u = tid & 127;
        const int warp = tid >> 5, lane = tid & 31;
        const int j1 = (blockIdx.y - NFULL2) * 2 + g;
        float* RE = pool + g * 1024;
        float* IM = pool + TLEN + g * 1024;
        {
            const int beta = (u >> 3) + ((u & 7) << 4);
            const float xic = 0.0125f;
            const float i2s = 5000.0f;
            float v0r, v0i, v1r, v1i;
#pragma unroll
            for (int h2 = 0; h2 < 2; h2++) {
                int bin = -98 + beta + 128 * h2;
                float f = (float)bin / 2048.0f;
                float dd = f - xic;
                float ps = __expf(-dd * dd * i2s);
                float vr, vi;
                if (j1 < N1F) {
                    int kb = bin & 2047;
                    int a = kb & 7, b = (kb >> 3) & 7, c = (kb >> 6) & 7, d = (kb >> 9) & 3;
                    int p = SW((a << 8) | (b << 5) | (c << 2) | d);
                    vr = g_u1h_re[n][j1][p] * ps;
                    vi = g_u1h_im[n][j1][p] * ps;
                } else {
                    int s5 = UW_SLOT(bin & 511);
                    vr = 4.0f * g_uwr[n][j1 - N1F][s5] * ps;
                    vi = 4.0f * g_uwi[n][j1 - N1F][s5] * ps;
                }
                if (h2 == 0) { v0r = vr; v0i = vi; } else { v1r = vr; v1i = vi; }
            }
            float xr[8], xi[8];
#pragma unroll
            for (int s = 0; s < 8; s++) {
                xr[s] = v0r + C8c[s] * v1r - S8c[s] * v1i;
                xi[s] = v0i + C8c[s] * v1i + S8c[s] * v1r;
            }
            int base = SW10(8 * u);
            ((float4*)(RE + base))[0] = make_float4(xr[0], xr[1], xr[2], xr[3]);
            ((float4*)(RE + base))[1] = make_float4(xr[4], xr[5], xr[6], xr[7]);
            ((float4*)(IM + base))[0] = make_float4(xi[0], xi[1], xi[2], xi[3]);
            ((float4*)(IM + base))[1] = make_float4(xi[4], xi[5], xi[6], xi[7]);
        }
        __syncthreads();
        {
            int gam = u >> 3, j = u & 7;
            int base = 64 * gam + j;
            float xr[8], xi[8];
#pragma unroll
            for (int d = 0; d < 8; d++) { int p = SW10(base + 8 * d); xr[d] = RE[p]; xi[d] = IM[p]; }
            float ws2, wc2;
            __sincosf((float)j * (TWO_PI / 64.0f), &ws2, &wc2);
            twiddle8(xr, xi, wc2, ws2);
            dft8(xr, xi, 1.0f);
#pragma unroll
            for (int d = 0; d < 8; d++) { int p = SW10(base + 8 * d); RE[p] = xr[d]; IM[p] = xi[d]; }
        }
        __syncthreads();
        float pr[KB], pi[KB], wrc, wrs;
        {
            const int r = u & 63, h = u >> 6;
            const int j = r & 7, m = r >> 3;
            float sn, cs;
            __sincosf((float)r * (TWO_PI / 1024.0f), &sn, &cs);
            wrc = cs; wrs = sn;
            float er[8], ei[8], qr[8], qi[8];
            float cr = 1.0f, ci = 0.0f;
#pragma unroll
            for (int gm = 0; gm < 16; gm++) {
                int p = SW10(64 * gm + 8 * m + j);
                float br = RE[p], bi = IM[p];
                float tr = br * cr - bi * ci;
                float ti = br * ci + bi * cr;
                if ((gm & 1) == 0) { er[gm >> 1] = tr; ei[gm >> 1] = ti; }
                else               { qr[gm >> 1] = tr; qi[gm >> 1] = ti; }
                float nc = cr * wrc - ci * wrs; ci = cr * wrs + ci * wrc; cr = nc;
            }
            dft8(er, ei, 1.0f);
            dft8(qr, qi, 1.0f);
            float sg = h ? -1.0f : 1.0f;
            float U[8];
#pragma unroll
            for (int s = 0; s < 8; s++) {
                float wr = sg * C16t[s], wi = sg * S16t[s];
                float zr = er[s] + wr * qr[s] - wi * qi[s];
                float zi = ei[s] + wr * qi[s] + wi * qr[s];
                U[s] = sqrtf(zr * zr + zi * zi) * invT;
            }
            float I0 = 0.f, I1r = 0.f, I1i = 0.f, I2r = 0.f, I2i = 0.f, I3r = 0.f, I3i = 0.f;
#pragma unroll
            for (int s = 0; s < 8; s++) {
                I0  += U[s];
                I1r += U[s] * C16t[s];            I1i -= U[s] * S16t[s];
                I2r += U[s] * C16t[(2 * s) & 15]; I2i -= U[s] * S16t[(2 * s) & 15];
                I3r += U[s] * C16t[(3 * s) & 15]; I3i -= U[s] * S16t[(3 * s) & 15];
            }
            float w1r = wrc, w1i = -wrs;
            float w2r = w1r * w1r - w1i * w1i, w2i = 2.0f * w1r * w1i;
            float w3r = w2r * w1r - w2i * w1i, w3i = w2r * w1i + w2i * w1r;
            float sg2 = h ? -1.0f : 1.0f;
            pr[0] = I0;                                   pi[0] = 0.0f;
            pr[1] = sg2 * (I1r * w1r - I1i * w1i);        pi[1] = sg2 * (I1r * w1i + I1i * w1r);
            pr[2] = (I2r * w2r - I2i * w2i);              pi[2] = (I2r * w2i + I2i * w2r);
            pr[3] = sg2 * (I3r * w3r - I3i * w3i);        pi[3] = sg2 * (I3r * w3i + I3i * w3r);
        }
        {
            float rows[7] = {pr[0], pr[1], pr[2], pr[3], pi[1], pi[2], pi[3]};
#pragma unroll
            for (int rr = 0; rr < 7; rr++) {
                float v = rows[rr];
#pragma unroll
                for (int o = 16; o; o >>= 1) v += __shfl_xor_sync(0xFFFFFFFFu, v, o);
                if (lane == 0) scw[warp][rr] = v;
            }
        }
        __syncthreads();
        {
            const int h = u >> 6;
            float cbv[7];
#pragma unroll
            for (int rr = 0; rr < 7; rr++)
                cbv[rr] = 2.0f * (scw[4 * g][rr] + scw[4 * g + 1][rr]
                                + scw[4 * g + 2][rr] + scw[4 * g + 3][rr]);
            float sg = h ? -1.0f : 1.0f;
            float e1r = wrc, e1i = wrs;
            float e2r = e1r * e1r - e1i * e1i, e2i = 2.0f * e1r * e1i;
            float e3r = e2r * e1r - e2i * e1i, e3i = e2r * e1i + e2i * e1r;
            float d0 = cbv[0];
            float d1r = sg * PH1 * (cbv[1] * e1r - cbv[4] * e1i);
            float d1i = sg * PH1 * (cbv[1] * e1i + cbv[4] * e1r);
            float d2r = PH2 * (cbv[2] * e2r - cbv[5] * e2i);
            float d2i = PH2 * (cbv[2] * e2i + cbv[5] * e2r);
            float d3r = sg * PH3 * (cbv[3] * e3r - cbv[6] * e3i);
            float d3i = sg * PH3 * (cbv[3] * e3i + cbv[6] * e3r);
            float s = 0.0f;
#pragma unroll
            for (int sI = 0; sI < 8; sI++) {
                float acc = d1r * C16t[sI] - d1i * S16t[sI]
                          + d2r * C16t[(2 * sI) & 15] - d2i * S16t[(2 * sI) & 15]
                          + d3r * C16t[(3 * sI) & 15] - d3i * S16t[(3 * sI) & 15];
                s += __logf((d0 + 2.0f * acc) * invT + 1e-6f);
            }
#pragma unroll
            for (int o = 16; o; o >>= 1) s += __shfl_xor_sync(0xFFFFFFFFu, s, o);
            if (lane == 0) redw[warp] = s;
        }
        __syncthreads();
        if (u == 0) {
            float tot = (redw[4 * g] + redw[4 * g + 1] + redw[4 * g + 2] + redw[4 * g + 3])
                        * (1.0f / 1024.0f);
            out[((n / NCH) * NCOEF + N1 + NFULL2 + j1) * NCH + (n % NCH)] = tot;
        }
        return;
    }
    // ------- k=6..9 windowed: 512-pt path, 4 groups x 64 thr -------
    {
        const int g = tid >> 6, u = tid & 63;
        const int warp = tid >> 5, lane = tid & 31;
        const int wp = (blockIdx.y - NFULL2 - NWIN5 / 2) * 4 + g;   // 0..239
        int k, j1;
        if (wp < 48)       { k = 6; j1 = wp; }
        else if (wp < 104) { k = 7; j1 = wp - 48; }
        else if (wp < 168) { k = 8; j1 = wp - 104; }
        else               { k = 9; j1 = wp - 168; }
        const int b_lo = (k == 6) ? -49 : (k == 7) ? -26 : (k == 8) ? -13 : -7;
        float* RE = pool + g * 512;
        float* IM = pool + TLEN + g * 512;
        float xr[8], xi[8];
        {
            const int base = (u >> 3) + ((u & 7) << 3);
            const float xic = 0.4f * exp2f(-(float)k);
            const float sg = 0.8f * xic;
            const float i2s = 1.0f / (2.0f * sg * sg);
            float v0r, v0i, v1r, v1i;
#pragma unroll
            for (int h = 0; h < 2; h++) {
                int bin = b_lo + base + 64 * h;
                float f = (float)bin / 2048.0f;
                float dd = f - xic;
                float ps = __expf(-dd * dd * i2s);
                float vr, vi;
                if (j1 < N1F) {
                    int kb = bin & 2047;
                    int a = kb & 7, b = (kb >> 3) & 7, c = (kb >> 6) & 7, d = (kb >> 9) & 3;
                    int p = SW((a << 8) | (b << 5) | (c << 2) | d);
                    vr = g_u1h_re[n][j1][p] * ps;
                    vi = g_u1h_im[n][j1][p] * ps;
                } else {
                    int s5 = UW_SLOT(bin & 511);
                    vr = 4.0f * g_uwr[n][j1 - N1F][s5] * ps;
                    vi = 4.0f * g_uwi[n][j1 - N1F][s5] * ps;
                }
                if (h == 0) { v0r = vr; v0i = vi; } else { v1r = vr; v1i = vi; }
            }
#pragma unroll
            for (int s = 0; s < 8; s++) {
                xr[s] = v0r + C8c[s] * v1r - S8c[s] * v1i;
                xi[s] = v0i + C8c[s] * v1i + S8c[s] * v1r;
            }
        }
        {
            int p0 = SW5(8 * u);
            ((float4*)(RE + p0))[0] = make_float4(xr[0], xr[1], xr[2], xr[3]);
            ((float4*)(RE + p0))[1] = make_float4(xr[4], xr[5], xr[6], xr[7]);
            ((float4*)(IM + p0))[0] = make_float4(xi[0], xi[1], xi[2], xi[3]);
            ((float4*)(IM + p0))[1] = make_float4(xi[4], xi[5], xi[6], xi[7]);
        }
        __syncthreads();
        {
            int j = u & 7;
            int base = ((u >> 3) << 6) + j;
#pragma unroll
            for (int m = 0; m < 8; m++) { int p = SW5(base + 8 * m); xr[m] = RE[p]; xi[m] = IM[p]; }
            float ws2, wc2;
            __sincosf((float)j * (TWO_PI / 64.0f), &ws2, &wc2);
            twiddle8(xr, xi, wc2, ws2);
            dft8(xr, xi, 1.0f);
#pragma unroll
            for (int m = 0; m < 8; m++) { int p = SW5(base + 8 * m); RE[p] = xr[m]; IM[p] = xi[m]; }
        }
        __syncthreads();
        float pr[KB], pi[KB], wc, ws;
        {
#pragma unroll
            for (int m = 0; m < 8; m++) { int p = SW5(u + 64 * m); xr[m] = RE[p]; xi[m] = IM[p]; }
            __sincosf((float)u * (TWO_PI / 512.0f), &ws, &wc);
            twiddle8(xr, xi, wc, ws);
            dft8(xr, xi, 1.0f);
            float U[8];
#pragma unroll
            for (int s = 0; s < 8; s++)
                U[s] = sqrtf(xr[s] * xr[s] + xi[s] * xi[s]) * invT;
            real_dft4(U, wc, ws, pr, pi);
        }
        {
            float rows[7] = {pr[0], pr[1], pr[2], pr[3], pi[1], pi[2], pi[3]};
#pragma unroll
            for (int r = 0; r < 7; r++) {
                float v = rows[r];
#pragma unroll
                for (int o = 16; o; o >>= 1) v += __shfl_xor_sync(0xFFFFFFFFu, v, o);
                if (lane == 0) scw[warp][r] = v;
            }
        }
        __syncthreads();
        {
            float cbv[7];
#pragma unroll
            for (int r = 0; r < 7; r++)
                cbv[r] = 4.0f * (scw[2 * g][r] + scw[2 * g + 1][r]);
            float d0 = cbv[0];
            float c1r = cbv[1], c2r = cbv[2], c3r = cbv[3];
            float c1i = cbv[4], c2i = cbv[5], c3i = cbv[6];
            float e2r = wc * wc - ws * ws, e2i = 2.0f * wc * ws;
            float e3r = e2r * wc - e2i * ws, e3i = e2r * ws + e2i * wc;
            float d1r = (c1r * wc - c1i * ws) * PH1, d1i = (c1r * ws + c1i * wc) * PH1;
            float d2r = (c2r * e2r - c2i * e2i) * PH2, d2i = (c2r * e2i + c2i * e2r) * PH2;
            float d3r = (c3r * e3r - c3i * e3i) * PH3, d3i = (c3r * e3i + c3i * e3r) * PH3;
            float s = 0.0f;
#pragma unroll
            for (int m = 0; m < 8; m++) {
                float acc = d1r * C8c[m] - d1i * S8c[m]
                          + d2r * C8c[(2 * m) & 7] - d2i * S8c[(2 * m) & 7]
                          + d3r * C8c[(3 * m) & 7] - d3i * S8c[(3 * m) & 7];
                s += __logf((d0 + 2.0f * acc) * invT + 1e-6f);
            }
#pragma unroll
            for (int o = 16; o; o >>= 1) s += __shfl_xor_sync(0xFFFFFFFFu, s, o);
            if (lane == 0) redw[warp] = s;
        }
        __syncthreads();
        if (u == 0) {
            float tot = (redw[2 * g] + redw[2 * g + 1]) * (1.0f / 512.0f);
            out[((n / NCH) * NCOEF + N1 + NFULL2 + NWIN5 + wp) * NCH + (n % NCH)] = tot;
        }
    }
}

// ---------------- launcher ----------------
extern "C" void kernel_launch(void* const* d_in, const int* in_sizes, int n_in,
                              void* d_out, int out_size) {
    const float* x = (const float*)d_in[0];   // [8, 2048, 6] f32
    float* out = (float*)d_out;               // [8, 440, 6] f32
    prep_kernel<<<NSAMP + NFILT, NT>>>(x);
    stage1m_kernel<<<dim3(NSAMP, N1F + N1W / 4), NT>>>(out);
    stage2m_kernel<<<dim3(NSAMP, NFULL2 + NWIN5 / 2 + NWIN / 4), NT>>>(out);
}